// round 16
// baseline (speedup 1.0000x reference)
#include <cuda_runtime.h>
#include <cuda_bf16.h>
#include <cstdint>

// 21x21 circular box filter on (8,1,2048,2048) fp32, separable, fused.
// Phase A: vertical running box-sums global -> smem (thread per halo column),
//          21-deep register ring (each input row loaded once); thread->column
//          map shifted by 22 so every warp's LDG is one aligned 128B line.
// Phase B: horizontal sliding window, 8 outputs per lane (3.5x read amp):
//          half-warp per row, 7 LDS.128 per lane, 2 STG.128.
//          VS=164 (stride = 4 mod 32 words) makes the two half-warps'
//          bank groups disjoint -> every LDS.128 at the 4-wavefront minimum.

#define H  2048
#define W  2048
#define NB 8
#define R  10
#define KW (2*R + 1)        // 21
#define TX 128
#define TY 32
#define NC (TX + 2*R)       // 148 halo columns
#define CSHIFT 22           // thread t -> column t-22: warp loads line-aligned
#define VS 164              // smem row stride (floats); 164 % 32 == 4
#define THREADS 256

__global__ __launch_bounds__(THREADS, 6)
void box_filter_kernel(const float* __restrict__ in, float* __restrict__ out)
{
    __shared__ float vert[TY * VS];   // 32*164*4 = 20,992 B

    const int t  = threadIdx.x;
    const int bx = blockIdx.x;
    const int by = blockIdx.y;
    const int bz = blockIdx.z;

    const float* img  = in  + (size_t)bz * (size_t)(H * W);
    float*       outg = out + (size_t)bz * (size_t)(H * W);

    const int tileX = bx * TX;
    const int tileY = by * TY;

    // ---------------- Phase A: vertical running sums (global -> smem) ---------
    // Column c = t - 22 (c in [0,148)); gx = tileX + t - 32 -> warp w loads the
    // aligned 128B line [tileX - 32 + 32w, +32 floats). Ring buffer: each of the
    // 52 input rows loaded exactly once per column.
    if (t >= CSHIFT && t < CSHIFT + NC) {
        const int c  = t - CSHIFT;
        const int gx = (tileX + c - R) & (W - 1);
        const int y0 = tileY - R;
        const float* colp = img + gx;

        float buf[KW];
        float s = 0.0f;

        if (y0 >= 0 && y0 + TY + 2 * R <= H) {
            // Interior: wrap-free, immediate offsets off one base pointer.
            const float* p = colp + (size_t)y0 * W;

            #pragma unroll
            for (int j = 0; j < KW; j++) { buf[j] = p[j * W]; s += buf[j]; }
            vert[c] = s;

            #pragma unroll
            for (int i = 1; i < TY; i++) {
                const int slot = (i - 1) % KW;       // compile-time after unroll
                const float nv = p[(i + 2 * R) * W];
                s += nv - buf[slot];
                buf[slot] = nv;
                vert[i * VS + c] = s;
            }
        } else {
            // Boundary tiles (by==0 or by==63): masked row addressing.
            #pragma unroll
            for (int j = 0; j < KW; j++) {
                buf[j] = colp[((y0 + j) & (H - 1)) * W];
                s += buf[j];
            }
            vert[c] = s;

            #pragma unroll
            for (int i = 1; i < TY; i++) {
                const int slot = (i - 1) % KW;
                const float nv = colp[((y0 + 2 * R + i) & (H - 1)) * W];
                s += nv - buf[slot];
                buf[slot] = nv;
                vert[i * VS + c] = s;
            }
        }
    }
    __syncthreads();

    // ---------------- Phase B: horizontal sliding window (smem -> global) -----
    // Half-warp per row: lane = (half, l), l in [0,16). Lane computes outputs
    // 8l..8l+7 of row r from vert[r][8l .. 8l+27] (7 quads), running sum.
    const int lane = t & 31;
    const int wp   = t >> 5;
    const int half = lane >> 4;       // 0 or 1
    const int l    = lane & 15;

    #pragma unroll
    for (int it = 0; it < 2; it++) {
        const int r = wp * 4 + it * 2 + half;
        const float* rowp = vert + r * VS + 8 * l;

        float e[28];
        #pragma unroll
        for (int j = 0; j < 7; j++) {
            const float4 q = *reinterpret_cast<const float4*>(rowp + 4 * j);
            e[4 * j + 0] = q.x;
            e[4 * j + 1] = q.y;
            e[4 * j + 2] = q.z;
            e[4 * j + 3] = q.w;
        }

        float s = e[0];
        #pragma unroll
        for (int j = 1; j <= 20; j++) s += e[j];

        float* op = outg + (size_t)(tileY + r) * W + tileX + 8 * l;

        float4 oA;
        oA.x = s;
        s += e[21] - e[0];  oA.y = s;
        s += e[22] - e[1];  oA.z = s;
        s += e[23] - e[2];  oA.w = s;
        *reinterpret_cast<float4*>(op) = oA;

        float4 oB;
        s += e[24] - e[3];  oB.x = s;
        s += e[25] - e[4];  oB.y = s;
        s += e[26] - e[5];  oB.z = s;
        s += e[27] - e[6];  oB.w = s;
        *reinterpret_cast<float4*>(op + 4) = oB;
    }
}

extern "C" void kernel_launch(void* const* d_in, const int* in_sizes, int n_in,
                              void* d_out, int out_size)
{
    const float* x = (const float*)d_in[0];
    float* out = (float*)d_out;

    dim3 grid(W / TX, H / TY, NB);   // (16, 64, 8) = 8192 blocks
    box_filter_kernel<<<grid, THREADS>>>(x, out);
}

// round 17
// speedup vs baseline: 1.2173x; 1.2173x over previous
#include <cuda_runtime.h>
#include <cuda_bf16.h>
#include <cstdint>

// 21x21 circular box filter on (8,1,2048,2048) fp32, separable, fused.
// Phase A: vertical running box-sums global -> smem, thread per halo column
//          (276 of 288 threads = 96% active), 21-deep register ring
//          (each input row loaded exactly once per column).
// Phase B: horizontal sliding window, 4 outputs/lane from 6 contiguous-lane
//          LDS.128 (4-wavefront each), 64 (row x chunk) tasks over 9 warps,
//          direct STG.128.

#define H  2048
#define W  2048
#define NB 8
#define R  10
#define KW (2*R + 1)        // 21
#define TX 256
#define TY 32
#define NC (TX + 2*R)       // 276 halo columns
#define VS 280              // smem row stride (floats), 16B-aligned
#define THREADS 288

__global__ __launch_bounds__(THREADS)
void box_filter_kernel(const float* __restrict__ in, float* __restrict__ out)
{
    __shared__ float vert[TY * VS];   // 32*280*4 = 35,840 B

    const int t  = threadIdx.x;
    const int bx = blockIdx.x;
    const int by = blockIdx.y;
    const int bz = blockIdx.z;

    const float* img  = in  + (size_t)bz * (size_t)(H * W);
    float*       outg = out + (size_t)bz * (size_t)(H * W);

    const int tileX = bx * TX;
    const int tileY = by * TY;

    // ---------------- Phase A: vertical running sums (global -> smem) ---------
    // Thread t -> halo column t (t < 276). Ring buffer: each of the 52 input
    // rows loaded exactly once per column.
    if (t < NC) {
        const int gx = (tileX + t - R) & (W - 1);
        const int y0 = tileY - R;
        const float* colp = img + gx;

        float buf[KW];
        float s = 0.0f;

        if (y0 >= 0 && y0 + TY + 2 * R <= H) {
            // Interior: wrap-free, immediate offsets off one base pointer.
            const float* p = colp + (size_t)y0 * W;

            #pragma unroll
            for (int j = 0; j < KW; j++) { buf[j] = p[j * W]; s += buf[j]; }
            vert[t] = s;

            #pragma unroll
            for (int i = 1; i < TY; i++) {
                const int slot = (i - 1) % KW;       // compile-time after unroll
                const float nv = p[(i + 2 * R) * W];
                s += nv - buf[slot];
                buf[slot] = nv;
                vert[i * VS + t] = s;
            }
        } else {
            // Boundary tiles (by==0 or by==63): masked row addressing.
            #pragma unroll
            for (int j = 0; j < KW; j++) {
                buf[j] = colp[((y0 + j) & (H - 1)) * W];
                s += buf[j];
            }
            vert[t] = s;

            #pragma unroll
            for (int i = 1; i < TY; i++) {
                const int slot = (i - 1) % KW;
                const float nv = colp[((y0 + 2 * R + i) & (H - 1)) * W];
                s += nv - buf[slot];
                buf[slot] = nv;
                vert[i * VS + t] = s;
            }
        }
    }
    __syncthreads();

    // ---------------- Phase B: horizontal sliding window (smem -> global) -----
    // 64 tasks = 32 rows x 2 chunks of 128 outputs; warp per task.
    // Lane l -> outputs b+4l..b+4l+3 from vert[r][b+4l .. b+4l+23] (6 quads).
    // Lanes contiguous (4l spacing) -> each LDS.128 = 4 wavefronts (minimum).
    const int lane = t & 31;
    const int wp   = t >> 5;

    for (int k = wp; k < 2 * TY; k += THREADS / 32) {
        const int r = k >> 1;
        const int b = (k & 1) << 7;            // 0 or 128
        const float* rowp = vert + r * VS + b + 4 * lane;

        float e[24];
        #pragma unroll
        for (int j = 0; j < 6; j++) {
            const float4 q = *reinterpret_cast<const float4*>(rowp + 4 * j);
            e[4 * j + 0] = q.x;
            e[4 * j + 1] = q.y;
            e[4 * j + 2] = q.z;
            e[4 * j + 3] = q.w;
        }

        float s = e[0];
        #pragma unroll
        for (int j = 1; j <= 20; j++) s += e[j];

        float4 o;
        o.x = s;
        s += e[21] - e[0];  o.y = s;
        s += e[22] - e[1];  o.z = s;
        s += e[23] - e[2];  o.w = s;

        *reinterpret_cast<float4*>(
            outg + (size_t)(tileY + r) * W + tileX + b + 4 * lane) = o;
    }
}

extern "C" void kernel_launch(void* const* d_in, const int* in_sizes, int n_in,
                              void* d_out, int out_size)
{
    const float* x = (const float*)d_in[0];
    float* out = (float*)d_out;

    dim3 grid(W / TX, H / TY, NB);   // (8, 64, 8) = 4096 blocks
    box_filter_kernel<<<grid, THREADS>>>(x, out);
}